// round 11
// baseline (speedup 1.0000x reference)
#include <cuda_runtime.h>
#include <cuda_fp16.h>
#include <math.h>
#include <stdint.h>

#define B_ROWS 16384
#define IN_DIM 1280
#define BELLY  1024
#define SCALE  512
#define NBINS  100
#define NPAT   10
#define LEVELS 12

#define OFF_Z  0
#define OFF_TL (B_ROWS * SCALE)
#define OFF_PL (OFF_TL + B_ROWS * NBINS)
#define OFF_TC (OFF_PL + B_ROWS * NBINS * NPAT)
#define OFF_CV (OFF_TC + B_ROWS)

#define NC_PAD 1152   // combined G3 weight rows: [0,100)=Wt, [128,1128)=Wp, rest 0
#define NDOTBLK (BELLY / 128)   // 8 column blocks in G1

// ---------------------------------------------------------------------------
// scratch (static device globals)
// ---------------------------------------------------------------------------
__device__ __half gFhi[B_ROWS * IN_DIM];
__device__ __half gFlo[B_ROWS * IN_DIM];
__device__ __half gHhi[B_ROWS * BELLY];
__device__ __half gZhi[B_ROWS * SCALE];
__device__ __half gW1hi[BELLY * IN_DIM];
__device__ __half gW1lo[BELLY * IN_DIM];
__device__ __half gW2hi[SCALE * BELLY];
__device__ __half gWchi[NC_PAD * SCALE];
__device__ float  gBc[NC_PAD];
__device__ float  gU[BELLY];               // u = W2 @ w_pos
__device__ float  gDotPart[NDOTBLK * B_ROWS]; // per-colblock dot partials
__device__ float  g_shift[B_ROWS];
__device__ int    g_maxpos;

// ---------------------------------------------------------------------------
// helpers
// ---------------------------------------------------------------------------
__device__ __forceinline__ uint32_t smem_u32(const void* p) {
    uint32_t a;
    asm("{ .reg .u64 t; cvta.to.shared.u64 t, %1; cvt.u32.u64 %0, t; }" : "=r"(a) : "l"(p));
    return a;
}
__device__ __forceinline__ void cp16(uint32_t s, const void* g) {
    asm volatile("cp.async.cg.shared.global [%0], [%1], 16;" :: "r"(s), "l"(g));
}
#define CP_COMMIT() asm volatile("cp.async.commit_group;" ::: "memory")
#define SWZ128(o) ((o) ^ (((o) >> 3) & 0x70))

__device__ __forceinline__ void ldsm4(uint32_t* r, uint32_t addr) {
    asm volatile("ldmatrix.sync.aligned.m8n8.x4.shared.b16 {%0,%1,%2,%3}, [%4];"
                 : "=r"(r[0]), "=r"(r[1]), "=r"(r[2]), "=r"(r[3]) : "r"(addr));
}
__device__ __forceinline__ void mma16816(float* c, const uint32_t* a, const uint32_t* b) {
    asm volatile("mma.sync.aligned.m16n8k16.row.col.f32.f16.f16.f32 "
                 "{%0,%1,%2,%3}, {%4,%5,%6,%7}, {%8,%9}, {%0,%1,%2,%3};"
                 : "+f"(c[0]), "+f"(c[1]), "+f"(c[2]), "+f"(c[3])
                 : "r"(a[0]), "r"(a[1]), "r"(a[2]), "r"(a[3]), "r"(b[0]), "r"(b[1]));
}

// CTA tile 128x128, BK=64, 3-stage pipeline, 128 threads (4 warps 2x2).
#define STAGE_SZ    16384
#define SMEM_B_OFF  49152
#define SMEM_BYTES  (98304 + 2048)

struct GemmParams {
    const __half* a0; const __half* a1; const __half* a2;
    const __half* b0; const __half* b1; const __half* b2;
    int K;
    int nseg;           // 1 or 3 (lo segs first, hi*hi last)
    const float* bias;
    float* outF;        // mode 1: plain; mode 3: tl
    float* outF2;       // mode 3: pl
    __half* out_hi;     // mode 0
    const float* u;     // mode 0: dot vector
    float* dotPart;     // mode 0: per-colblock partials [gridDim.x][B_ROWS]
    int ldo;
    int mode;           // 0: bias+relu+split(hi)+dot, 1: plain f32, 3: combined tl/pl
};

// ---------------------------------------------------------------------------
// HMMA split GEMM, 128x128 CTA tile, 64x64 warp tile (2m x 2n), 2 CTAs/SM.
// nseg=3: a0*b0 (hi*lo), a1*b1 (lo*hi), [acc/=4096], a2*b2 (hi*hi)
// nseg=1: a0*b0 (hi*hi). Epilogue scales by 1/256 (weight hi pre-scale).
// ---------------------------------------------------------------------------
__global__ void __launch_bounds__(128, 2) gemm_hmma_kernel(GemmParams p) {
    extern __shared__ char smraw[];
    uint32_t sb = (smem_u32(smraw) + 1023) & ~1023u;

    const int tid  = threadIdx.x;
    const int lane = tid & 31;
    const int wid  = tid >> 5;
    const int wm   = wid & 1;       // 2 warps in m (64 rows each)
    const int wn   = wid >> 1;      // 2 warps in n (64 cols each)
    const int bm   = blockIdx.y * 128;
    const int bn   = blockIdx.x * 128;
    const int K    = p.K;
    const int KT   = K >> 6;
    const int TOT  = p.nseg * KT;
    const int rescale_at = (p.nseg > 1) ? (p.nseg - 1) * KT : -1;

    const __half* APtr[3] = { p.a0, p.a1, p.a2 };
    const __half* BPtr[3] = { p.b0, p.b1, p.b2 };

    // loader geometry: 128 threads, rows (tid>>3)+16*i, 16B chunk (tid&7)
    const int ldrow = tid >> 3;      // 0..15
    const int ldq   = tid & 7;
    uint32_t ldoff[8];
    #pragma unroll
    for (int i = 0; i < 8; i++)
        ldoff[i] = SWZ128((ldrow + i * 16) * 128 + ldq * 16);

    // ldmatrix base addresses (ks=0); per-ks address = base ^ (ks<<5)
    uint32_t aAddr[4];
    #pragma unroll
    for (int mt = 0; mt < 4; mt++) {
        int row = wm * 64 + mt * 16 + (lane & 15);
        aAddr[mt] = sb + SWZ128(row * 128 + ((lane >> 4) << 4));
    }
    uint32_t bAddr[4];
    #pragma unroll
    for (int ntp = 0; ntp < 4; ntp++) {
        int row = wn * 64 + ntp * 16 + ((lane >> 4) << 3) + (lane & 7);
        bAddr[ntp] = sb + SMEM_B_OFF + SWZ128(row * 128 + (((lane >> 3) & 1) << 4));
    }

    float acc[4][8][4];
    #pragma unroll
    for (int mt = 0; mt < 4; mt++)
        #pragma unroll
        for (int nt = 0; nt < 8; nt++)
            #pragma unroll
            for (int i = 0; i < 4; i++) acc[mt][nt][i] = 0.0f;

    auto load_tile = [&](int t, int stage) {
        int seg = t / KT;
        int kt  = t - seg * KT;
        const __half* A = APtr[seg] + (size_t)bm * K + kt * 64 + ldq * 8;
        const __half* B = BPtr[seg] + (size_t)bn * K + kt * 64 + ldq * 8;
        uint32_t aB = sb + stage * STAGE_SZ;
        uint32_t bB = sb + SMEM_B_OFF + stage * STAGE_SZ;
        #pragma unroll
        for (int i = 0; i < 8; i++)
            cp16(aB + ldoff[i], A + (size_t)(ldrow + i * 16) * K);
        #pragma unroll
        for (int i = 0; i < 8; i++)
            cp16(bB + ldoff[i], B + (size_t)(ldrow + i * 16) * K);
        CP_COMMIT();
    };

    load_tile(0, 0);
    if (TOT > 1) load_tile(1, 1);
    else         CP_COMMIT();

    for (int t = 0; t < TOT; t++) {
        if (t == TOT - 1) asm volatile("cp.async.wait_group 0;" ::: "memory");
        else              asm volatile("cp.async.wait_group 1;" ::: "memory");
        __syncthreads();

        if (t + 2 < TOT) load_tile(t + 2, (t + 2) % 3);

        if (t == rescale_at) {
            #pragma unroll
            for (int mt = 0; mt < 4; mt++)
                #pragma unroll
                for (int nt = 0; nt < 8; nt++)
                    #pragma unroll
                    for (int i = 0; i < 4; i++)
                        acc[mt][nt][i] *= (1.0f / 4096.0f);
        }

        const int stage = t % 3;
        const uint32_t soff = (uint32_t)(stage * STAGE_SZ);

        #pragma unroll
        for (int ks = 0; ks < 4; ks++) {
            const uint32_t kx = (uint32_t)(ks << 5);
            uint32_t afr[4][4];
            #pragma unroll
            for (int mt = 0; mt < 4; mt++)
                ldsm4(afr[mt], (aAddr[mt] ^ kx) + soff);
            uint32_t bfr[8][2];
            #pragma unroll
            for (int ntp = 0; ntp < 4; ntp++) {
                uint32_t r[4];
                ldsm4(r, (bAddr[ntp] ^ kx) + soff);
                bfr[2 * ntp][0]     = r[0];
                bfr[2 * ntp][1]     = r[1];
                bfr[2 * ntp + 1][0] = r[2];
                bfr[2 * ntp + 1][1] = r[3];
            }
            #pragma unroll
            for (int mt = 0; mt < 4; mt++)
                #pragma unroll
                for (int nt = 0; nt < 8; nt++)
                    mma16816(acc[mt][nt], afr[mt], bfr[nt]);
        }
    }

    // ---------------- epilogue ----------------
    const float inv256 = 1.0f / 256.0f;
    const int gID = lane >> 2, tig = lane & 3;

    if (p.mode == 0) {
        // bias + relu + write hi fp16 + accumulate per-row dot partials
        float dpart[4][2];
        #pragma unroll
        for (int mt = 0; mt < 4; mt++) { dpart[mt][0] = 0.0f; dpart[mt][1] = 0.0f; }

        #pragma unroll
        for (int mt = 0; mt < 4; mt++) {
            #pragma unroll
            for (int nt = 0; nt < 8; nt++) {
                int r0 = bm + wm * 64 + mt * 16 + gID;
                int c0 = bn + wn * 64 + nt * 8 + tig * 2;
                float b0 = p.bias[c0], b1 = p.bias[c0 + 1];
                float u0 = p.u[c0],    u1 = p.u[c0 + 1];
                #pragma unroll
                for (int h = 0; h < 2; h++) {
                    int rr = r0 + h * 8;
                    float x0 = fmaxf(acc[mt][nt][h * 2 + 0] * inv256 + b0, 0.0f);
                    float x1 = fmaxf(acc[mt][nt][h * 2 + 1] * inv256 + b1, 0.0f);
                    dpart[mt][h] += x0 * u0 + x1 * u1;
                    size_t o = (size_t)rr * p.ldo + c0;
                    *reinterpret_cast<__half2*>(p.out_hi + o) =
                        __halves2half2(__float2half(x0), __float2half(x1));
                }
            }
        }
        // reduce over the 4 col-threads (tig) per row
        #pragma unroll
        for (int mt = 0; mt < 4; mt++)
            #pragma unroll
            for (int h = 0; h < 2; h++) {
                float s = dpart[mt][h];
                s += __shfl_xor_sync(0xffffffffu, s, 1);
                s += __shfl_xor_sync(0xffffffffu, s, 2);
                dpart[mt][h] = s;
            }
        // reduce over the 2 n-warps via smem (reuse pipeline stage 0 after barrier)
        __syncthreads();
        float* sm_dot = reinterpret_cast<float*>(smraw + (sb - smem_u32(smraw)));
        if (tig == 0) {
            #pragma unroll
            for (int mt = 0; mt < 4; mt++)
                #pragma unroll
                for (int h = 0; h < 2; h++) {
                    int rloc = wm * 64 + mt * 16 + h * 8 + gID;
                    sm_dot[wn * 128 + rloc] = dpart[mt][h];
                }
        }
        __syncthreads();
        // 128 threads: one row each
        p.dotPart[(size_t)blockIdx.x * B_ROWS + bm + tid] =
            sm_dot[tid] + sm_dot[128 + tid];
        return;
    }

    #pragma unroll
    for (int mt = 0; mt < 4; mt++) {
        #pragma unroll
        for (int nt = 0; nt < 8; nt++) {
            int r0 = bm + wm * 64 + mt * 16 + gID;
            int c0 = bn + wn * 64 + nt * 8 + tig * 2;
            float v[4];
            #pragma unroll
            for (int i = 0; i < 4; i++) v[i] = acc[mt][nt][i] * inv256;

            if (p.mode == 1) {
                #pragma unroll
                for (int h = 0; h < 2; h++) {
                    int rr = r0 + h * 8;
                    size_t o = (size_t)rr * p.ldo + c0;
                    float2 st = { v[h * 2 + 0], v[h * 2 + 1] };
                    *reinterpret_cast<float2*>(p.outF + o) = st;
                }
            } else { // mode 3: combined tl / pl
                float b0 = p.bias[c0], b1 = p.bias[c0 + 1];
                #pragma unroll
                for (int h = 0; h < 2; h++) {
                    int rr = r0 + h * 8;
                    float x0 = v[h * 2 + 0] + b0;
                    float x1 = v[h * 2 + 1] + b1;
                    if (c0 < NBINS) {
                        p.outF[(size_t)rr * NBINS + c0]     = x0;
                        p.outF[(size_t)rr * NBINS + c0 + 1] = x1;
                    } else if (c0 >= 128 && c0 < 128 + NBINS * NPAT) {
                        p.outF2[(size_t)rr * (NBINS * NPAT) + (c0 - 128)]     = x0;
                        p.outF2[(size_t)rr * (NBINS * NPAT) + (c0 - 128) + 1] = x1;
                    }
                }
            }
        }
    }
}

// ---------------------------------------------------------------------------
// split / pack kernels
// ---------------------------------------------------------------------------
__global__ void split_act_kernel(const float* __restrict__ x,
                                 __half* __restrict__ hi, __half* __restrict__ lo, int n4) {
    int i = blockIdx.x * blockDim.x + threadIdx.x;
    if (i >= n4) return;
    float4 v = reinterpret_cast<const float4*>(x)[i];
    float vv[4] = { v.x, v.y, v.z, v.w };
    __half hh[4], ll[4];
    #pragma unroll
    for (int j = 0; j < 4; j++) {
        hh[j] = __float2half(vv[j]);
        ll[j] = __float2half((vv[j] - __half2float(hh[j])) * 4096.0f);
    }
    reinterpret_cast<__half2*>(hi)[i * 2]     = __halves2half2(hh[0], hh[1]);
    reinterpret_cast<__half2*>(hi)[i * 2 + 1] = __halves2half2(hh[2], hh[3]);
    reinterpret_cast<__half2*>(lo)[i * 2]     = __halves2half2(ll[0], ll[1]);
    reinterpret_cast<__half2*>(lo)[i * 2 + 1] = __halves2half2(ll[2], ll[3]);
}

// W [K,N] fp32 -> [Npad,K] fp16 hi(+lo) transposed (hi x256, residual x4096)
__global__ void split_weight_t_kernel(const float* __restrict__ W,
                                      __half* __restrict__ bhi, __half* __restrict__ blo,
                                      int K, int N, int Npad) {
    int idx = blockIdx.x * blockDim.x + threadIdx.x;
    if (idx >= Npad * K) return;
    int n = idx / K, k = idx - n * K;
    float w = (n < N) ? W[(size_t)k * N + n] * 256.0f : 0.0f;
    __half h = __float2half(w);
    bhi[idx] = h;
    if (blo) blo[idx] = __float2half((w - __half2float(h)) * 4096.0f);
}

// combined G3 weight pack (hi only, x256) + bias pack
__global__ void pack_wc_kernel(const float* __restrict__ Wt, const float* __restrict__ Wp,
                               const float* __restrict__ bt, const float* __restrict__ bp,
                               __half* __restrict__ wch, float* __restrict__ bc) {
    int idx = blockIdx.x * blockDim.x + threadIdx.x;
    if (idx < NC_PAD * SCALE) {
        int n = idx / SCALE, k = idx - n * SCALE;
        float w = 0.0f;
        if (n < NBINS)                           w = Wt[(size_t)k * NBINS + n];
        else if (n >= 128 && n < 128 + NBINS * NPAT)
                                                 w = Wp[(size_t)k * (NBINS * NPAT) + (n - 128)];
        wch[idx] = __float2half(w * 256.0f);
    }
    if (idx < NC_PAD) {
        float v = 0.0f;
        if (idx < NBINS) v = bt[idx];
        else if (idx >= 128 && idx < 128 + NBINS * NPAT) v = bp[idx - 128];
        bc[idx] = v;
    }
}

// u = W2 @ w_pos  (fp32; one warp per output row)
__global__ __launch_bounds__(256) void u_kernel(const float* __restrict__ W2,
                                                const float* __restrict__ w_pos,
                                                float* __restrict__ u) {
    int row  = blockIdx.x * 8 + (threadIdx.x >> 5);
    int lane = threadIdx.x & 31;
    if (row >= BELLY) return;
    float s = 0.0f;
    for (int n = lane; n < SCALE; n += 32)
        s += W2[(size_t)row * SCALE + n] * w_pos[n];
    #pragma unroll
    for (int o = 16; o; o >>= 1) s += __shfl_xor_sync(0xffffffffu, s, o);
    if (lane == 0) u[row] = s;
}

// ---------------------------------------------------------------------------
// timestep class + max (XLA folds t/1000*100 -> t*0.1f == t/10 exactly)
// ---------------------------------------------------------------------------
__global__ __launch_bounds__(1024) void classmax_kernel(const int* __restrict__ timesteps,
                                                        float* __restrict__ out_tc) {
    __shared__ int smax[32];
    int tid = threadIdx.x;
    int local_max = 0;
    for (int i = tid; i < B_ROWS; i += 1024) {
        int t = timesteps[i];
        int c = t / 10;
        c = min(max(c, 0), NBINS - 1);
        out_tc[i] = (float)c;
        local_max = max(local_max, c);
    }
    #pragma unroll
    for (int o = 16; o; o >>= 1)
        local_max = max(local_max, __shfl_xor_sync(0xffffffffu, local_max, o));
    if ((tid & 31) == 0) smax[tid >> 5] = local_max;
    __syncthreads();
    if (tid < 32) {
        int v = smax[tid];
        #pragma unroll
        for (int o = 16; o; o >>= 1)
            v = max(v, __shfl_xor_sync(0xffffffffu, v, o));
        if (tid == 0) g_maxpos = v + 1;
    }
}

// ---------------------------------------------------------------------------
// normalize z rows + shift from summed dot partials + write z fp16 (hi only)
// ---------------------------------------------------------------------------
__global__ __launch_bounds__(128) void normshift_kernel(float* __restrict__ z,
                                                        const float* __restrict__ dotPart,
                                                        const float* __restrict__ b_pos,
                                                        __half* __restrict__ zhi) {
    int row = blockIdx.x;
    float* zr = z + (size_t)row * SCALE;
    int tid = threadIdx.x;

    float4 v = *reinterpret_cast<float4*>(&zr[tid * 4]);
    float ss = v.x * v.x + v.y * v.y + v.z * v.z + v.w * v.w;

    __shared__ float sss[4];
    #pragma unroll
    for (int o = 16; o; o >>= 1)
        ss += __shfl_xor_sync(0xffffffffu, ss, o);
    if ((tid & 31) == 0) sss[tid >> 5] = ss;
    __syncthreads();
    ss = sss[0] + sss[1] + sss[2] + sss[3];

    float norm = sqrtf(ss);
    float inv  = __fdiv_rn(1.0f, fmaxf(norm, 1e-12f));
    v.x *= inv; v.y *= inv; v.z *= inv; v.w *= inv;
    *reinterpret_cast<float4*>(&zr[tid * 4]) = v;

    size_t base = (size_t)row * SCALE + tid * 4;
    __half2 h01 = __halves2half2(__float2half(v.x), __float2half(v.y));
    __half2 h23 = __halves2half2(__float2half(v.z), __float2half(v.w));
    *reinterpret_cast<__half2*>(zhi + base)     = h01;
    *reinterpret_cast<__half2*>(zhi + base + 2) = h23;

    if (tid == 0) {
        float dot = 0.0f;
        #pragma unroll
        for (int j = 0; j < NDOTBLK; j++)
            dot += dotPart[(size_t)j * B_ROWS + row];
        g_shift[row] = tanhf(dot * inv + b_pos[0]) * 0.3f;
    }
}

// ---------------------------------------------------------------------------
// Cantor staircase
// ---------------------------------------------------------------------------
__global__ __launch_bounds__(256) void cantor_kernel(const float* __restrict__ tc,
                                                     const float* __restrict__ alpha_p,
                                                     float* __restrict__ cv) {
    int i = blockIdx.x * blockDim.x + threadIdx.x;
    if (i >= B_ROWS) return;

    float alpha  = *alpha_p;
    int   maxpos = g_maxpos;
    float pos    = tc[i];
    float denomp = fmaxf((float)(maxpos - 1), 1.0f);
    float xb     = (maxpos > 1) ? __fdiv_rn(pos, denomp) : pos;
    xb = fminf(fmaxf(xb, 1e-6f), 1.0f - 1e-6f);
    float x = xb + g_shift[i];
    x = fminf(fmaxf(x, 1e-6f), 1.0f - 1e-6f);

    float Cx = 0.0f, w = 0.5f;
    const float inv_tau = 1.0f / (0.25f + 1e-8f);
    #pragma unroll
    for (int l = 0; l < LEVELS; l++) {
        float y  = x * 3.0f;
        float d0 = y - 0.5f, d1 = y - 1.5f, d2 = y - 2.5f;
        float l0 = -(d0 * d0) * inv_tau;
        float l1 = -(d1 * d1) * inv_tau;
        float l2 = -(d2 * d2) * inv_tau;
        float m  = fmaxf(l0, fmaxf(l1, l2));
        float e0 = expf(l0 - m), e1 = expf(l1 - m), e2 = expf(l2 - m);
        float bit = __fdiv_rn(e1 * alpha + e2, e0 + e1 + e2);
        Cx += bit * w;
        x = y - floorf(y);
        w *= 0.5f;
    }
    cv[i] = fminf(fmaxf(Cx, 0.0f), 1.0f);
}

// ---------------------------------------------------------------------------
// kernel_launch
// ---------------------------------------------------------------------------
extern "C" void kernel_launch(void* const* d_in, const int* in_sizes, int n_in,
                              void* d_out, int out_size) {
    const float* features = (const float*)d_in[0];
    const int*   timesteps= (const int*)  d_in[1];
    const float* W1       = (const float*)d_in[2];
    const float* b1       = (const float*)d_in[3];
    const float* W2       = (const float*)d_in[4];
    const float* Wt       = (const float*)d_in[5];
    const float* bt       = (const float*)d_in[6];
    const float* Wp       = (const float*)d_in[7];
    const float* bp       = (const float*)d_in[8];
    const float* w_pos    = (const float*)d_in[9];
    const float* b_pos    = (const float*)d_in[10];
    const float* alpha    = (const float*)d_in[11];

    float* out = (float*)d_out;
    float* z   = out + OFF_Z;
    float* tl  = out + OFF_TL;
    float* pl  = out + OFF_PL;
    float* tc  = out + OFF_TC;
    float* cv  = out + OFF_CV;

    cudaFuncSetAttribute(gemm_hmma_kernel,
                         cudaFuncAttributeMaxDynamicSharedMemorySize, SMEM_BYTES);

    __half *fhi, *flo, *hhi, *zhi;
    __half *w1h, *w1l, *w2h, *wch;
    float  *bc, *uPtr, *dotPartPtr;
    cudaGetSymbolAddress((void**)&fhi, gFhi);  cudaGetSymbolAddress((void**)&flo, gFlo);
    cudaGetSymbolAddress((void**)&hhi, gHhi);
    cudaGetSymbolAddress((void**)&zhi, gZhi);
    cudaGetSymbolAddress((void**)&w1h, gW1hi); cudaGetSymbolAddress((void**)&w1l, gW1lo);
    cudaGetSymbolAddress((void**)&w2h, gW2hi);
    cudaGetSymbolAddress((void**)&wch, gWchi);
    cudaGetSymbolAddress((void**)&bc,  gBc);
    cudaGetSymbolAddress((void**)&uPtr, gU);
    cudaGetSymbolAddress((void**)&dotPartPtr, gDotPart);

    // 1: u = W2 @ w_pos
    u_kernel<<<BELLY / 8, 256>>>(W2, w_pos, uPtr);
    // 2: W1 split
    { int n = BELLY * IN_DIM;
      split_weight_t_kernel<<<(n + 255) / 256, 256>>>(W1, w1h, w1l, IN_DIM, BELLY, BELLY); }
    // 3: features split (vectorized x4)
    { int n4 = B_ROWS * IN_DIM / 4;
      split_act_kernel<<<(n4 + 255) / 256, 256>>>(features, fhi, flo, n4); }
    // 4: G1 (3-seg): H = relu(F @ W1 + b1) -> fp16 hi + fused dot partials
    {
        GemmParams p = {};
        p.a0 = fhi; p.a1 = flo; p.a2 = fhi;
        p.b0 = w1l; p.b1 = w1h; p.b2 = w1h;
        p.K = IN_DIM; p.nseg = 3; p.bias = b1;
        p.out_hi = hhi; p.u = uPtr; p.dotPart = dotPartPtr;
        p.ldo = BELLY; p.mode = 0;
        gemm_hmma_kernel<<<dim3(BELLY / 128, B_ROWS / 128), 128, SMEM_BYTES>>>(p);
    }
    // 5: W2 hi-only split
    { int n = SCALE * BELLY;
      split_weight_t_kernel<<<(n + 255) / 256, 256>>>(W2, w2h, nullptr, BELLY, SCALE, SCALE); }
    // 6: G2 (1-seg): z_raw = H_hi @ W2_hi (fp32 out)
    {
        GemmParams p = {};
        p.a0 = hhi; p.a1 = hhi; p.a2 = hhi;
        p.b0 = w2h; p.b1 = w2h; p.b2 = w2h;
        p.K = BELLY; p.nseg = 1; p.outF = z; p.ldo = SCALE; p.mode = 1;
        gemm_hmma_kernel<<<dim3(SCALE / 128, B_ROWS / 128), 128, SMEM_BYTES>>>(p);
    }
    // 7: normalize z + shift (sums dot partials)
    normshift_kernel<<<B_ROWS, 128>>>(z, dotPartPtr, b_pos, zhi);
    // 8: G3 weight/bias pack
    { int n = NC_PAD * SCALE;
      pack_wc_kernel<<<(n + 255) / 256, 256>>>(Wt, Wp, bt, bp, wch, bc); }
    // 9: timestep class + max
    classmax_kernel<<<1, 1024>>>(timesteps, tc);
    // 10: G3 (1-seg): combined [tl | pl] = z @ Wc + bc
    {
        GemmParams p = {};
        p.a0 = zhi; p.a1 = zhi; p.a2 = zhi;
        p.b0 = wch; p.b1 = wch; p.b2 = wch;
        p.K = SCALE; p.nseg = 1; p.bias = bc;
        p.outF = tl; p.outF2 = pl; p.mode = 3;
        gemm_hmma_kernel<<<dim3(NC_PAD / 128, B_ROWS / 128), 128, SMEM_BYTES>>>(p);
    }
    // 11: cantor
    cantor_kernel<<<(B_ROWS + 255) / 256, 256>>>(tc, alpha, cv);
}

// round 12
// speedup vs baseline: 1.0390x; 1.0390x over previous
#include <cuda_runtime.h>
#include <cuda_fp16.h>
#include <math.h>
#include <stdint.h>

#define B_ROWS 16384
#define IN_DIM 1280
#define BELLY  1024
#define SCALE  512
#define NBINS  100
#define NPAT   10
#define LEVELS 12

#define OFF_Z  0
#define OFF_TL (B_ROWS * SCALE)
#define OFF_PL (OFF_TL + B_ROWS * NBINS)
#define OFF_TC (OFF_PL + B_ROWS * NBINS * NPAT)
#define OFF_CV (OFF_TC + B_ROWS)

#define NC_PAD 1152
#define NDOTBLK (BELLY / 128)

// ---------------------------------------------------------------------------
// scratch
// ---------------------------------------------------------------------------
__device__ __half gFhi[B_ROWS * IN_DIM];
__device__ __half gFlo[B_ROWS * IN_DIM];
__device__ __half gHhi[B_ROWS * BELLY];
__device__ __half gZhi[B_ROWS * SCALE];
__device__ __half gW1hi[BELLY * IN_DIM];
__device__ __half gW1lo[BELLY * IN_DIM];
__device__ __half gW2hi[SCALE * BELLY];
__device__ __half gWchi[NC_PAD * SCALE];
__device__ float  gBc[NC_PAD];
__device__ float  gU[BELLY];
__device__ float  gDotPart[NDOTBLK * B_ROWS];
__device__ float  g_shift[B_ROWS];
__device__ int    g_maxpos;

// ---------------------------------------------------------------------------
// helpers
// ---------------------------------------------------------------------------
__device__ __forceinline__ uint32_t smem_u32(const void* p) {
    uint32_t a;
    asm("{ .reg .u64 t; cvta.to.shared.u64 t, %1; cvt.u32.u64 %0, t; }" : "=r"(a) : "l"(p));
    return a;
}
__device__ __forceinline__ void cp16(uint32_t s, const void* g) {
    asm volatile("cp.async.cg.shared.global [%0], [%1], 16;" :: "r"(s), "l"(g));
}
#define CP_COMMIT() asm volatile("cp.async.commit_group;" ::: "memory")
#define SWZ128(o) ((o) ^ (((o) >> 3) & 0x70))
#define SWZ64(o)  ((o) ^ (((o) >> 3) & 0x30))

__device__ __forceinline__ void ldsm4(uint32_t* r, uint32_t addr) {
    asm volatile("ldmatrix.sync.aligned.m8n8.x4.shared.b16 {%0,%1,%2,%3}, [%4];"
                 : "=r"(r[0]), "=r"(r[1]), "=r"(r[2]), "=r"(r[3]) : "r"(addr));
}
__device__ __forceinline__ void mma16816(float* c, const uint32_t* a, const uint32_t* b) {
    asm volatile("mma.sync.aligned.m16n8k16.row.col.f32.f16.f16.f32 "
                 "{%0,%1,%2,%3}, {%4,%5,%6,%7}, {%8,%9}, {%0,%1,%2,%3};"
                 : "+f"(c[0]), "+f"(c[1]), "+f"(c[2]), "+f"(c[3])
                 : "r"(a[0]), "r"(a[1]), "r"(a[2]), "r"(a[3]), "r"(b[0]), "r"(b[1]));
}

// ======================= fused G1 kernel (BK=32, SW64) ======================
// stage = [Ahi 8K | Alo 8K | Bhi 8K | Blo 8K] = 32KB, 3 stages
#define FSTAGE   32768
#define FP_ALO   8192
#define FP_BHI   16384
#define FP_BLO   24576
#define FSMEM_BYTES (98304 + 1024)

struct FusedParams {
    const __half* ahi; const __half* alo;
    const __half* bhi; const __half* blo;
    int K;
    const float* bias;
    __half* out_hi;
    const float* u;
    float* dotPart;
    int ldo;
};

__global__ void __launch_bounds__(128, 2) gemm_fused_kernel(FusedParams p) {
    extern __shared__ char smraw[];
    uint32_t sb = (smem_u32(smraw) + 1023) & ~1023u;

    const int tid  = threadIdx.x;
    const int lane = tid & 31;
    const int wid  = tid >> 5;
    const int wm   = wid & 1;
    const int wn   = wid >> 1;
    const int bm   = blockIdx.y * 128;
    const int bn   = blockIdx.x * 128;
    const int K    = p.K;
    const int KT   = K >> 5;     // k-tiles of 32

    // loader: ldrow = tid>>2 (0..31), ldq = tid&3; rows ldrow+32i
    const int ldrow = tid >> 2;
    const int ldq   = tid & 3;
    uint32_t ldoff[4];
    #pragma unroll
    for (int i = 0; i < 4; i++)
        ldoff[i] = SWZ64((ldrow + i * 32) * 64 + ldq * 16);

    // fragment base addresses (kstep 0); kstep1 = ^32 (valid since c in {0,1})
    uint32_t aAddr[4];
    #pragma unroll
    for (int mt = 0; mt < 4; mt++) {
        int row = wm * 64 + mt * 16 + (lane & 15);
        aAddr[mt] = sb + SWZ64(row * 64 + ((lane >> 4) << 4));
    }
    uint32_t bAddr[4];
    #pragma unroll
    for (int ntp = 0; ntp < 4; ntp++) {
        int row = wn * 64 + ntp * 16 + ((lane >> 4) << 3) + (lane & 7);
        bAddr[ntp] = sb + FP_BHI + SWZ64(row * 64 + (((lane >> 3) & 1) << 4));
    }

    float acc[4][8][4];
    #pragma unroll
    for (int mt = 0; mt < 4; mt++)
        #pragma unroll
        for (int nt = 0; nt < 8; nt++)
            #pragma unroll
            for (int i = 0; i < 4; i++) acc[mt][nt][i] = 0.0f;

    auto load_tile = [&](int kt, int stage) {
        uint32_t st = sb + stage * FSTAGE;
        const __half* Ah = p.ahi + (size_t)bm * K + kt * 32 + ldq * 8;
        const __half* Al = p.alo + (size_t)bm * K + kt * 32 + ldq * 8;
        const __half* Bh = p.bhi + (size_t)bn * K + kt * 32 + ldq * 8;
        const __half* Bl = p.blo + (size_t)bn * K + kt * 32 + ldq * 8;
        #pragma unroll
        for (int i = 0; i < 4; i++) {
            size_t roff = (size_t)(ldrow + i * 32) * K;
            cp16(st + ldoff[i],            Ah + roff);
            cp16(st + FP_ALO + ldoff[i],   Al + roff);
            cp16(st + FP_BHI + ldoff[i],   Bh + roff);
            cp16(st + FP_BLO + ldoff[i],   Bl + roff);
        }
        CP_COMMIT();
    };

    load_tile(0, 0);
    if (KT > 1) load_tile(1, 1);
    else        CP_COMMIT();

    for (int t = 0; t < KT; t++) {
        if (t == KT - 1) asm volatile("cp.async.wait_group 0;" ::: "memory");
        else             asm volatile("cp.async.wait_group 1;" ::: "memory");
        __syncthreads();

        if (t + 2 < KT) load_tile(t + 2, (t + 2) % 3);

        const uint32_t soff = (uint32_t)((t % 3) * FSTAGE);

        #pragma unroll
        for (int ks = 0; ks < 2; ks++) {
            const uint32_t kx = (uint32_t)(ks << 5);

            uint32_t ahi[4][4];
            #pragma unroll
            for (int mt = 0; mt < 4; mt++)
                ldsm4(ahi[mt], (aAddr[mt] ^ kx) + soff);

            // --- product 1: a_hi * b_lo ---
            {
                uint32_t bfr[8][2];
                #pragma unroll
                for (int ntp = 0; ntp < 4; ntp++) {
                    uint32_t r[4];
                    ldsm4(r, (bAddr[ntp] ^ kx) + soff + (FP_BLO - FP_BHI));
                    bfr[2 * ntp][0] = r[0]; bfr[2 * ntp][1] = r[1];
                    bfr[2 * ntp + 1][0] = r[2]; bfr[2 * ntp + 1][1] = r[3];
                }
                #pragma unroll
                for (int mt = 0; mt < 4; mt++)
                    #pragma unroll
                    for (int nt = 0; nt < 8; nt++)
                        mma16816(acc[mt][nt], ahi[mt], bfr[nt]);
            }

            // --- products 2+3: a_lo * b_hi, a_hi * b_hi ---
            {
                uint32_t bhi[8][2];
                #pragma unroll
                for (int ntp = 0; ntp < 4; ntp++) {
                    uint32_t r[4];
                    ldsm4(r, (bAddr[ntp] ^ kx) + soff);
                    bhi[2 * ntp][0] = r[0]; bhi[2 * ntp][1] = r[1];
                    bhi[2 * ntp + 1][0] = r[2]; bhi[2 * ntp + 1][1] = r[3];
                }
                uint32_t alo[4][4];
                #pragma unroll
                for (int mt = 0; mt < 4; mt++)
                    ldsm4(alo[mt], (aAddr[mt] ^ kx) + soff + FP_ALO);
                #pragma unroll
                for (int mt = 0; mt < 4; mt++)
                    #pragma unroll
                    for (int nt = 0; nt < 8; nt++)
                        mma16816(acc[mt][nt], alo[mt], bhi[nt]);
                #pragma unroll
                for (int mt = 0; mt < 4; mt++)
                    #pragma unroll
                    for (int nt = 0; nt < 8; nt++)
                        mma16816(acc[mt][nt], ahi[mt], bhi[nt]);
            }
        }
    }

    // ------- epilogue: bias + relu + fp16 hi + fused dot partials -------
    const float inv256 = 1.0f / 256.0f;
    const int gID = lane >> 2, tig = lane & 3;

    float dpart[4][2];
    #pragma unroll
    for (int mt = 0; mt < 4; mt++) { dpart[mt][0] = 0.0f; dpart[mt][1] = 0.0f; }

    #pragma unroll
    for (int mt = 0; mt < 4; mt++) {
        #pragma unroll
        for (int nt = 0; nt < 8; nt++) {
            int r0 = bm + wm * 64 + mt * 16 + gID;
            int c0 = bn + wn * 64 + nt * 8 + tig * 2;
            float b0 = p.bias[c0], b1 = p.bias[c0 + 1];
            float u0 = p.u[c0],    u1 = p.u[c0 + 1];
            #pragma unroll
            for (int h = 0; h < 2; h++) {
                int rr = r0 + h * 8;
                float x0 = fmaxf(acc[mt][nt][h * 2 + 0] * inv256 + b0, 0.0f);
                float x1 = fmaxf(acc[mt][nt][h * 2 + 1] * inv256 + b1, 0.0f);
                dpart[mt][h] += x0 * u0 + x1 * u1;
                size_t o = (size_t)rr * p.ldo + c0;
                *reinterpret_cast<__half2*>(p.out_hi + o) =
                    __halves2half2(__float2half(x0), __float2half(x1));
            }
        }
    }
    #pragma unroll
    for (int mt = 0; mt < 4; mt++)
        #pragma unroll
        for (int h = 0; h < 2; h++) {
            float s = dpart[mt][h];
            s += __shfl_xor_sync(0xffffffffu, s, 1);
            s += __shfl_xor_sync(0xffffffffu, s, 2);
            dpart[mt][h] = s;
        }
    __syncthreads();
    float* sm_dot = reinterpret_cast<float*>(smraw + (sb - smem_u32(smraw)));
    if (tig == 0) {
        #pragma unroll
        for (int mt = 0; mt < 4; mt++)
            #pragma unroll
            for (int h = 0; h < 2; h++) {
                int rloc = wm * 64 + mt * 16 + h * 8 + gID;
                sm_dot[wn * 128 + rloc] = dpart[mt][h];
            }
    }
    __syncthreads();
    p.dotPart[(size_t)blockIdx.x * B_ROWS + bm + tid] = sm_dot[tid] + sm_dot[128 + tid];
}

// ======================= 1-seg kernel (G2/G3, BK=64, SW128) =================
#define STAGE_SZ    16384
#define SMEM_B_OFF  49152
#define SMEM_BYTES  (98304 + 2048)

struct GemmParams {
    const __half* a0;
    const __half* b0;
    int K;
    const float* bias;
    float* outF;        // mode 1: plain; mode 3: tl
    float* outF2;       // mode 3: pl
    int ldo;
    int mode;           // 1: plain f32, 3: combined tl/pl
};

__global__ void __launch_bounds__(128, 2) gemm_hmma_kernel(GemmParams p) {
    extern __shared__ char smraw[];
    uint32_t sb = (smem_u32(smraw) + 1023) & ~1023u;

    const int tid  = threadIdx.x;
    const int lane = tid & 31;
    const int wid  = tid >> 5;
    const int wm   = wid & 1;
    const int wn   = wid >> 1;
    const int bm   = blockIdx.y * 128;
    const int bn   = blockIdx.x * 128;
    const int K    = p.K;
    const int TOT  = K >> 6;

    const int ldrow = tid >> 3;
    const int ldq   = tid & 7;
    uint32_t ldoff[8];
    #pragma unroll
    for (int i = 0; i < 8; i++)
        ldoff[i] = SWZ128((ldrow + i * 16) * 128 + ldq * 16);

    uint32_t aAddr[4];
    #pragma unroll
    for (int mt = 0; mt < 4; mt++) {
        int row = wm * 64 + mt * 16 + (lane & 15);
        aAddr[mt] = sb + SWZ128(row * 128 + ((lane >> 4) << 4));
    }
    uint32_t bAddr[4];
    #pragma unroll
    for (int ntp = 0; ntp < 4; ntp++) {
        int row = wn * 64 + ntp * 16 + ((lane >> 4) << 3) + (lane & 7);
        bAddr[ntp] = sb + SMEM_B_OFF + SWZ128(row * 128 + (((lane >> 3) & 1) << 4));
    }

    float acc[4][8][4];
    #pragma unroll
    for (int mt = 0; mt < 4; mt++)
        #pragma unroll
        for (int nt = 0; nt < 8; nt++)
            #pragma unroll
            for (int i = 0; i < 4; i++) acc[mt][nt][i] = 0.0f;

    auto load_tile = [&](int kt, int stage) {
        const __half* A = p.a0 + (size_t)bm * K + kt * 64 + ldq * 8;
        const __half* B = p.b0 + (size_t)bn * K + kt * 64 + ldq * 8;
        uint32_t aB = sb + stage * STAGE_SZ;
        uint32_t bB = sb + SMEM_B_OFF + stage * STAGE_SZ;
        #pragma unroll
        for (int i = 0; i < 8; i++)
            cp16(aB + ldoff[i], A + (size_t)(ldrow + i * 16) * K);
        #pragma unroll
        for (int i = 0; i < 8; i++)
            cp16(bB + ldoff[i], B + (size_t)(ldrow + i * 16) * K);
        CP_COMMIT();
    };

    load_tile(0, 0);
    if (TOT > 1) load_tile(1, 1);
    else         CP_COMMIT();

    for (int t = 0; t < TOT; t++) {
        if (t == TOT - 1) asm volatile("cp.async.wait_group 0;" ::: "memory");
        else              asm volatile("cp.async.wait_group 1;" ::: "memory");
        __syncthreads();

        if (t + 2 < TOT) load_tile(t + 2, (t + 2) % 3);

        const uint32_t soff = (uint32_t)((t % 3) * STAGE_SZ);

        #pragma unroll
        for (int ks = 0; ks < 4; ks++) {
            const uint32_t kx = (uint32_t)(ks << 5);
            uint32_t afr[4][4];
            #pragma unroll
            for (int mt = 0; mt < 4; mt++)
                ldsm4(afr[mt], (aAddr[mt] ^ kx) + soff);
            uint32_t bfr[8][2];
            #pragma unroll
            for (int ntp = 0; ntp < 4; ntp++) {
                uint32_t r[4];
                ldsm4(r, (bAddr[ntp] ^ kx) + soff);
                bfr[2 * ntp][0] = r[0]; bfr[2 * ntp][1] = r[1];
                bfr[2 * ntp + 1][0] = r[2]; bfr[2 * ntp + 1][1] = r[3];
            }
            #pragma unroll
            for (int mt = 0; mt < 4; mt++)
                #pragma unroll
                for (int nt = 0; nt < 8; nt++)
                    mma16816(acc[mt][nt], afr[mt], bfr[nt]);
        }
    }

    const float inv256 = 1.0f / 256.0f;
    const int gID = lane >> 2, tig = lane & 3;
    #pragma unroll
    for (int mt = 0; mt < 4; mt++) {
        #pragma unroll
        for (int nt = 0; nt < 8; nt++) {
            int r0 = bm + wm * 64 + mt * 16 + gID;
            int c0 = bn + wn * 64 + nt * 8 + tig * 2;
            float v[4];
            #pragma unroll
            for (int i = 0; i < 4; i++) v[i] = acc[mt][nt][i] * inv256;

            if (p.mode == 1) {
                #pragma unroll
                for (int h = 0; h < 2; h++) {
                    int rr = r0 + h * 8;
                    size_t o = (size_t)rr * p.ldo + c0;
                    float2 st = { v[h * 2 + 0], v[h * 2 + 1] };
                    *reinterpret_cast<float2*>(p.outF + o) = st;
                }
            } else {
                float b0 = p.bias[c0], b1 = p.bias[c0 + 1];
                #pragma unroll
                for (int h = 0; h < 2; h++) {
                    int rr = r0 + h * 8;
                    float x0 = v[h * 2 + 0] + b0;
                    float x1 = v[h * 2 + 1] + b1;
                    if (c0 < NBINS) {
                        p.outF[(size_t)rr * NBINS + c0]     = x0;
                        p.outF[(size_t)rr * NBINS + c0 + 1] = x1;
                    } else if (c0 >= 128 && c0 < 128 + NBINS * NPAT) {
                        p.outF2[(size_t)rr * (NBINS * NPAT) + (c0 - 128)]     = x0;
                        p.outF2[(size_t)rr * (NBINS * NPAT) + (c0 - 128) + 1] = x1;
                    }
                }
            }
        }
    }
}

// ---------------------------------------------------------------------------
// split / pack kernels (lo residuals now UNSCALED)
// ---------------------------------------------------------------------------
__global__ void split_act_kernel(const float* __restrict__ x,
                                 __half* __restrict__ hi, __half* __restrict__ lo, int n4) {
    int i = blockIdx.x * blockDim.x + threadIdx.x;
    if (i >= n4) return;
    float4 v = reinterpret_cast<const float4*>(x)[i];
    float vv[4] = { v.x, v.y, v.z, v.w };
    __half hh[4], ll[4];
    #pragma unroll
    for (int j = 0; j < 4; j++) {
        hh[j] = __float2half(vv[j]);
        ll[j] = __float2half(vv[j] - __half2float(hh[j]));
    }
    reinterpret_cast<__half2*>(hi)[i * 2]     = __halves2half2(hh[0], hh[1]);
    reinterpret_cast<__half2*>(hi)[i * 2 + 1] = __halves2half2(hh[2], hh[3]);
    reinterpret_cast<__half2*>(lo)[i * 2]     = __halves2half2(ll[0], ll[1]);
    reinterpret_cast<__half2*>(lo)[i * 2 + 1] = __halves2half2(ll[2], ll[3]);
}

__global__ void split_weight_t_kernel(const float* __restrict__ W,
                                      __half* __restrict__ bhi, __half* __restrict__ blo,
                                      int K, int N, int Npad) {
    int idx = blockIdx.x * blockDim.x + threadIdx.x;
    if (idx >= Npad * K) return;
    int n = idx / K, k = idx - n * K;
    float w = (n < N) ? W[(size_t)k * N + n] * 256.0f : 0.0f;
    __half h = __float2half(w);
    bhi[idx] = h;
    if (blo) blo[idx] = __float2half(w - __half2float(h));
}

__global__ void pack_wc_kernel(const float* __restrict__ Wt, const float* __restrict__ Wp,
                               const float* __restrict__ bt, const float* __restrict__ bp,
                               __half* __restrict__ wch, float* __restrict__ bc) {
    int idx = blockIdx.x * blockDim.x + threadIdx.x;
    if (idx < NC_PAD * SCALE) {
        int n = idx / SCALE, k = idx - n * SCALE;
        float w = 0.0f;
        if (n < NBINS)                           w = Wt[(size_t)k * NBINS + n];
        else if (n >= 128 && n < 128 + NBINS * NPAT)
                                                 w = Wp[(size_t)k * (NBINS * NPAT) + (n - 128)];
        wch[idx] = __float2half(w * 256.0f);
    }
    if (idx < NC_PAD) {
        float v = 0.0f;
        if (idx < NBINS) v = bt[idx];
        else if (idx >= 128 && idx < 128 + NBINS * NPAT) v = bp[idx - 128];
        bc[idx] = v;
    }
}

__global__ __launch_bounds__(256) void u_kernel(const float* __restrict__ W2,
                                                const float* __restrict__ w_pos,
                                                float* __restrict__ u) {
    int row  = blockIdx.x * 8 + (threadIdx.x >> 5);
    int lane = threadIdx.x & 31;
    if (row >= BELLY) return;
    float s = 0.0f;
    for (int n = lane; n < SCALE; n += 32)
        s += W2[(size_t)row * SCALE + n] * w_pos[n];
    #pragma unroll
    for (int o = 16; o; o >>= 1) s += __shfl_xor_sync(0xffffffffu, s, o);
    if (lane == 0) u[row] = s;
}

// ---------------------------------------------------------------------------
__global__ __launch_bounds__(1024) void classmax_kernel(const int* __restrict__ timesteps,
                                                        float* __restrict__ out_tc) {
    __shared__ int smax[32];
    int tid = threadIdx.x;
    int local_max = 0;
    for (int i = tid; i < B_ROWS; i += 1024) {
        int t = timesteps[i];
        int c = t / 10;
        c = min(max(c, 0), NBINS - 1);
        out_tc[i] = (float)c;
        local_max = max(local_max, c);
    }
    #pragma unroll
    for (int o = 16; o; o >>= 1)
        local_max = max(local_max, __shfl_xor_sync(0xffffffffu, local_max, o));
    if ((tid & 31) == 0) smax[tid >> 5] = local_max;
    __syncthreads();
    if (tid < 32) {
        int v = smax[tid];
        #pragma unroll
        for (int o = 16; o; o >>= 1)
            v = max(v, __shfl_xor_sync(0xffffffffu, v, o));
        if (tid == 0) g_maxpos = v + 1;
    }
}

__global__ __launch_bounds__(128) void normshift_kernel(float* __restrict__ z,
                                                        const float* __restrict__ dotPart,
                                                        const float* __restrict__ b_pos,
                                                        __half* __restrict__ zhi) {
    int row = blockIdx.x;
    float* zr = z + (size_t)row * SCALE;
    int tid = threadIdx.x;

    float4 v = *reinterpret_cast<float4*>(&zr[tid * 4]);
    float ss = v.x * v.x + v.y * v.y + v.z * v.z + v.w * v.w;

    __shared__ float sss[4];
    #pragma unroll
    for (int o = 16; o; o >>= 1)
        ss += __shfl_xor_sync(0xffffffffu, ss, o);
    if ((tid & 31) == 0) sss[tid >> 5] = ss;
    __syncthreads();
    ss = sss[0] + sss[1] + sss[2] + sss[3];

    float norm = sqrtf(ss);
    float inv  = __fdiv_rn(1.0f, fmaxf(norm, 1e-12f));
    v.x *= inv; v.y *= inv; v.z *= inv; v.w *= inv;
    *reinterpret_cast<float4*>(&zr[tid * 4]) = v;

    size_t base = (size_t)row * SCALE + tid * 4;
    __half2 h01 = __halves2half2(__float2half(v.x), __float2half(v.y));
    __half2 h23 = __halves2half2(__float2half(v.z), __float2half(v.w));
    *reinterpret_cast<__half2*>(zhi + base)     = h01;
    *reinterpret_cast<__half2*>(zhi + base + 2) = h23;

    if (tid == 0) {
        float dot = 0.0f;
        #pragma unroll
        for (int j = 0; j < NDOTBLK; j++)
            dot += dotPart[(size_t)j * B_ROWS + row];
        g_shift[row] = tanhf(dot * inv + b_pos[0]) * 0.3f;
    }
}

__global__ __launch_bounds__(256) void cantor_kernel(const float* __restrict__ tc,
                                                     const float* __restrict__ alpha_p,
                                                     float* __restrict__ cv) {
    int i = blockIdx.x * blockDim.x + threadIdx.x;
    if (i >= B_ROWS) return;

    float alpha  = *alpha_p;
    int   maxpos = g_maxpos;
    float pos    = tc[i];
    float denomp = fmaxf((float)(maxpos - 1), 1.0f);
    float xb     = (maxpos > 1) ? __fdiv_rn(pos, denomp) : pos;
    xb = fminf(fmaxf(xb, 1e-6f), 1.0f - 1e-6f);
    float x = xb + g_shift[i];
    x = fminf(fmaxf(x, 1e-6f), 1.0f - 1e-6f);

    float Cx = 0.0f, w = 0.5f;
    const float inv_tau = 1.0f / (0.25f + 1e-8f);
    #pragma unroll
    for (int l = 0; l < LEVELS; l++) {
        float y  = x * 3.0f;
        float d0 = y - 0.5f, d1 = y - 1.5f, d2 = y - 2.5f;
        float l0 = -(d0 * d0) * inv_tau;
        float l1 = -(d1 * d1) * inv_tau;
        float l2 = -(d2 * d2) * inv_tau;
        float m  = fmaxf(l0, fmaxf(l1, l2));
        float e0 = expf(l0 - m), e1 = expf(l1 - m), e2 = expf(l2 - m);
        float bit = __fdiv_rn(e1 * alpha + e2, e0 + e1 + e2);
        Cx += bit * w;
        x = y - floorf(y);
        w *= 0.5f;
    }
    cv[i] = fminf(fmaxf(Cx, 0.0f), 1.0f);
}

// ---------------------------------------------------------------------------
// kernel_launch
// ---------------------------------------------------------------------------
extern "C" void kernel_launch(void* const* d_in, const int* in_sizes, int n_in,
                              void* d_out, int out_size) {
    const float* features = (const float*)d_in[0];
    const int*   timesteps= (const int*)  d_in[1];
    const float* W1       = (const float*)d_in[2];
    const float* b1       = (const float*)d_in[3];
    const float* W2       = (const float*)d_in[4];
    const float* Wt       = (const float*)d_in[5];
    const float* bt       = (const float*)d_in[6];
    const float* Wp       = (const float*)d_in[7];
    const float* bp       = (const float*)d_in[8];
    const float* w_pos    = (const float*)d_in[9];
    const float* b_pos    = (const float*)d_in[10];
    const float* alpha    = (const float*)d_in[11];

    float* out = (float*)d_out;
    float* z   = out + OFF_Z;
    float* tl  = out + OFF_TL;
    float* pl  = out + OFF_PL;
    float* tc  = out + OFF_TC;
    float* cv  = out + OFF_CV;

    cudaFuncSetAttribute(gemm_hmma_kernel,
                         cudaFuncAttributeMaxDynamicSharedMemorySize, SMEM_BYTES);
    cudaFuncSetAttribute(gemm_fused_kernel,
                         cudaFuncAttributeMaxDynamicSharedMemorySize, FSMEM_BYTES);

    __half *fhi, *flo, *hhi, *zhi;
    __half *w1h, *w1l, *w2h, *wch;
    float  *bc, *uPtr, *dotPartPtr;
    cudaGetSymbolAddress((void**)&fhi, gFhi);  cudaGetSymbolAddress((void**)&flo, gFlo);
    cudaGetSymbolAddress((void**)&hhi, gHhi);
    cudaGetSymbolAddress((void**)&zhi, gZhi);
    cudaGetSymbolAddress((void**)&w1h, gW1hi); cudaGetSymbolAddress((void**)&w1l, gW1lo);
    cudaGetSymbolAddress((void**)&w2h, gW2hi);
    cudaGetSymbolAddress((void**)&wch, gWchi);
    cudaGetSymbolAddress((void**)&bc,  gBc);
    cudaGetSymbolAddress((void**)&uPtr, gU);
    cudaGetSymbolAddress((void**)&dotPartPtr, gDotPart);

    // 1: u = W2 @ w_pos
    u_kernel<<<BELLY / 8, 256>>>(W2, w_pos, uPtr);
    // 2: W1 split (hi x256, lo unscaled residual)
    { int n = BELLY * IN_DIM;
      split_weight_t_kernel<<<(n + 255) / 256, 256>>>(W1, w1h, w1l, IN_DIM, BELLY, BELLY); }
    // 3: features split
    { int n4 = B_ROWS * IN_DIM / 4;
      split_act_kernel<<<(n4 + 255) / 256, 256>>>(features, fhi, flo, n4); }
    // 4: G1 fused (3 products, 1 pass): H = relu(F@W1+b1) -> hhi + dot partials
    {
        FusedParams p = {};
        p.ahi = fhi; p.alo = flo; p.bhi = w1h; p.blo = w1l;
        p.K = IN_DIM; p.bias = b1;
        p.out_hi = hhi; p.u = uPtr; p.dotPart = dotPartPtr; p.ldo = BELLY;
        gemm_fused_kernel<<<dim3(BELLY / 128, B_ROWS / 128), 128, FSMEM_BYTES>>>(p);
    }
    // 5: W2 hi-only split
    { int n = SCALE * BELLY;
      split_weight_t_kernel<<<(n + 255) / 256, 256>>>(W2, w2h, nullptr, BELLY, SCALE, SCALE); }
    // 6: G2 (1-seg): z_raw = H_hi @ W2_hi
    {
        GemmParams p = {};
        p.a0 = hhi; p.b0 = w2h;
        p.K = BELLY; p.outF = z; p.ldo = SCALE; p.mode = 1;
        gemm_hmma_kernel<<<dim3(SCALE / 128, B_ROWS / 128), 128, SMEM_BYTES>>>(p);
    }
    // 7: normalize z + shift
    normshift_kernel<<<B_ROWS, 128>>>(z, dotPartPtr, b_pos, zhi);
    // 8: G3 pack
    { int n = NC_PAD * SCALE;
      pack_wc_kernel<<<(n + 255) / 256, 256>>>(Wt, Wp, bt, bp, wch, bc); }
    // 9: class + max
    classmax_kernel<<<1, 1024>>>(timesteps, tc);
    // 10: G3 (1-seg): [tl | pl] = z @ Wc + bc
    {
        GemmParams p = {};
        p.a0 = zhi; p.b0 = wch;
        p.K = SCALE; p.bias = bc;
        p.outF = tl; p.outF2 = pl; p.mode = 3;
        gemm_hmma_kernel<<<dim3(NC_PAD / 128, B_ROWS / 128), 128, SMEM_BYTES>>>(p);
    }
    // 11: cantor
    cantor_kernel<<<(B_ROWS + 255) / 256, 256>>>(tc, alpha, cv);
}